// round 10
// baseline (speedup 1.0000x reference)
#include <cuda_runtime.h>
#include <math.h>
#include <stdint.h>

// Problem constants
#define D_MODEL 1024
#define NHEAD   16
#define DKH     64
#define NLAYER  8
#define FF_DIM  4096
#define BATCH   4
#define TGT     512
#define SRCL    256
#define VOCAB   32000
#define ROWS_X  (BATCH*TGT)   // 2048
#define ROWS_E  (BATCH*SRCL)  // 1024

// ---------------- scratch (device globals; no allocation allowed) ----------
__device__ float g_x   [ROWS_X*(size_t)D_MODEL];
__device__ float g_enc [ROWS_E*(size_t)D_MODEL];
__device__ float g_q   [ROWS_X*(size_t)D_MODEL];
__device__ float g_k   [ROWS_X*(size_t)D_MODEL];
__device__ float g_v   [ROWS_X*(size_t)D_MODEL];
__device__ float g_attn[ROWS_X*(size_t)D_MODEL];
__device__ float g_tmp [ROWS_X*(size_t)D_MODEL];
__device__ float g_ff  [ROWS_X*(size_t)FF_DIM];

// ---------------- positional encoding -------------------------------------
__device__ __forceinline__ float pe_val(int pos, int c) {
    int i2 = c & ~1;  // even index 2i
    float div = expf((float)i2 * (-9.210340371976184f / (float)D_MODEL)); // ln(10000)
    float ang = (float)pos * div;
    return (c & 1) ? cosf(ang) : sinf(ang);
}

// x[b,t,:] = emb[tgt[b,t],:] + pe(t,:)
__global__ void embed_kernel(const int* __restrict__ tgt,
                             const float* __restrict__ emb,
                             float* __restrict__ x) {
    int row = blockIdx.x;           // b*TGT + t
    int t = row % TGT;
    int token = tgt[row];
    const float* erow = emb + (size_t)token * D_MODEL;
    float* xrow = x + (size_t)row * D_MODEL;
    for (int c = threadIdx.x; c < D_MODEL; c += blockDim.x)
        xrow[c] = erow[c] + pe_val(t, c);
}

// enc[b,s,:] = src[b,s,:] + pe(s,:)
__global__ void encpe_kernel(const float* __restrict__ src,
                             float* __restrict__ enc) {
    int row = blockIdx.x;           // b*SRCL + s
    int s = row % SRCL;
    const float* srow = src + (size_t)row * D_MODEL;
    float* erow = enc + (size_t)row * D_MODEL;
    for (int c = threadIdx.x; c < D_MODEL; c += blockDim.x)
        erow[c] = srow[c] + pe_val(s, c);
}

// ---------------- SGEMM: C[M,N] = A[M,K] @ B[K,N] + bias (opt ReLU) --------
// 128x128 block tile, BK=8, 256 threads, 8x8 per-thread, register prefetch.
// Requires M%128==0, N%128==0, K%8==0 (holds for every GEMM in this model).
template<bool RELU>
__global__ __launch_bounds__(256, 2)
void sgemm_bias(const float* __restrict__ A, const float* __restrict__ B,
                const float* __restrict__ bias, float* __restrict__ C,
                int M, int N, int K) {
    __shared__ float As[8][128];
    __shared__ float Bs[8][128];
    const int bx = blockIdx.x;      // N tile
    const int by = blockIdx.y;      // M tile
    const int tid = threadIdx.x;

    const int arow = tid >> 1;            // 0..127
    const int acol = (tid & 1) * 4;       // 0 or 4
    const int brow = tid >> 5;            // 0..7
    const int bcol = (tid & 31) * 4;      // 0..124

    const float* Aptr = A + (size_t)(by * 128 + arow) * K + acol;
    const float* Bptr = B + (size_t)brow * N + (size_t)bx * 128 + bcol;

    const int tr = (tid >> 4) << 3;       // output row base within tile
    const int tc = (tid & 15) << 3;       // output col base within tile

    float acc[8][8];
    #pragma unroll
    for (int i = 0; i < 8; i++)
        #pragma unroll
        for (int j = 0; j < 8; j++) acc[i][j] = 0.f;

    float4 a4 = *(const float4*)Aptr;
    float4 b4 = *(const float4*)Bptr;

    for (int k0 = 0; k0 < K; k0 += 8) {
        As[acol + 0][arow] = a4.x;
        As[acol + 1][arow] = a4.y;
        As[acol + 2][arow] = a4.z;
        As[acol + 3][arow] = a4.w;
        *(float4*)&Bs[brow][bcol] = b4;
        __syncthreads();

        if (k0 + 8 < K) {
            Aptr += 8;
            Bptr += (size_t)8 * N;
            a4 = *(const float4*)Aptr;
            b4 = *(const float4*)Bptr;
        }

        #pragma unroll
        for (int kk = 0; kk < 8; kk++) {
            float ra[8], rb[8];
            #pragma unroll
            for (int i = 0; i < 8; i++) ra[i] = As[kk][tr + i];
            #pragma unroll
            for (int j = 0; j < 8; j++) rb[j] = Bs[kk][tc + j];
            #pragma unroll
            for (int i = 0; i < 8; i++)
                #pragma unroll
                for (int j = 0; j < 8; j++)
                    acc[i][j] += ra[i] * rb[j];
        }
        __syncthreads();
    }

    // epilogue: bias (+ReLU), vectorized stores
    #pragma unroll
    for (int i = 0; i < 8; i++) {
        float* crow = C + (size_t)(by * 128 + tr + i) * N + (size_t)bx * 128 + tc;
        #pragma unroll
        for (int j = 0; j < 8; j += 4) {
            float4 o;
            o.x = acc[i][j + 0] + bias[bx * 128 + tc + j + 0];
            o.y = acc[i][j + 1] + bias[bx * 128 + tc + j + 1];
            o.z = acc[i][j + 2] + bias[bx * 128 + tc + j + 2];
            o.w = acc[i][j + 3] + bias[bx * 128 + tc + j + 3];
            if (RELU) {
                o.x = fmaxf(o.x, 0.f); o.y = fmaxf(o.y, 0.f);
                o.z = fmaxf(o.z, 0.f); o.w = fmaxf(o.w, 0.f);
            }
            *(float4*)&crow[j] = o;
        }
    }
}

// ---------------- attention ------------------------------------------------
// grid: (TGT/8, NHEAD, BATCH), 256 threads. Block handles 8 query rows of one
// (b,h). Scores kept in smem; K/V streamed as 64-row tiles.
// MASKED: self-attn mask = (tgt[b,q]!=0) && (k<=q), else -1e9.
template<bool MASKED>
__global__ __launch_bounds__(256)
void attn_kernel(const float* __restrict__ q, const float* __restrict__ k,
                 const float* __restrict__ v, const int* __restrict__ tgt,
                 float* __restrict__ out, int Skv) {
    const int qt = blockIdx.x, h = blockIdx.y, b = blockIdx.z;
    const int qbase = qt * 8;
    const int tid = threadIdx.x;

    __shared__ float qs[8][DKH];
    __shared__ float ks[64][65];      // padded: conflict-free both axes
    __shared__ float sc[8][TGT];      // scores/probs (max Skv = 512)
    __shared__ int   rowok[8];

    // load q tile (+ row masks)
    for (int i = tid; i < 8 * DKH; i += 256) {
        int qi = i >> 6, d = i & 63;
        qs[qi][d] = q[((size_t)(b * TGT + qbase + qi)) * D_MODEL + h * DKH + d];
    }
    if (MASKED && tid < 8)
        rowok[tid] = (tgt[b * TGT + qbase + tid] != 0);
    __syncthreads();

    const int qi0 = tid >> 6;   // 0..3 (also handles qi0+4)
    const int kj  = tid & 63;

    // scores
    for (int kt = 0; kt < Skv; kt += 64) {
        for (int i = tid; i < 64 * 16; i += 256) {       // 1024 float4 loads
            int r = i >> 4, c4 = (i & 15) * 4;
            float4 f = *(const float4*)&k[((size_t)(b * Skv + kt + r)) * D_MODEL + h * DKH + c4];
            ks[r][c4 + 0] = f.x; ks[r][c4 + 1] = f.y;
            ks[r][c4 + 2] = f.z; ks[r][c4 + 3] = f.w;
        }
        __syncthreads();
        #pragma unroll
        for (int half = 0; half < 2; half++) {
            int qi = qi0 + half * 4;
            float acc = 0.f;
            #pragma unroll
            for (int d = 0; d < DKH; d++) acc += qs[qi][d] * ks[kj][d];
            float s = acc * 0.125f;      // 1/sqrt(64)
            int kglob = kt + kj;
            if (MASKED) {
                bool ok = (kglob <= qbase + qi) && rowok[qi];
                if (!ok) s = -1e9f;
            }
            sc[qi][kglob] = s;
        }
        __syncthreads();
    }

    // softmax: one warp per query row (8 warps)
    {
        int w = tid >> 5, lane = tid & 31;
        float m = -INFINITY;
        for (int j = lane; j < Skv; j += 32) m = fmaxf(m, sc[w][j]);
        #pragma unroll
        for (int o = 16; o; o >>= 1) m = fmaxf(m, __shfl_xor_sync(~0u, m, o));
        float ssum = 0.f;
        for (int j = lane; j < Skv; j += 32) {
            float e = __expf(sc[w][j] - m);
            sc[w][j] = e;
            ssum += e;
        }
        #pragma unroll
        for (int o = 16; o; o >>= 1) ssum += __shfl_xor_sync(~0u, ssum, o);
        float inv = 1.f / ssum;
        for (int j = lane; j < Skv; j += 32) sc[w][j] *= inv;
    }
    __syncthreads();

    // out = probs @ V  (reuse ks as V tile)
    const int d = tid & 63;
    float o0 = 0.f, o1 = 0.f;
    for (int kt = 0; kt < Skv; kt += 64) {
        for (int i = tid; i < 64 * 16; i += 256) {
            int r = i >> 4, c4 = (i & 15) * 4;
            float4 f = *(const float4*)&v[((size_t)(b * Skv + kt + r)) * D_MODEL + h * DKH + c4];
            ks[r][c4 + 0] = f.x; ks[r][c4 + 1] = f.y;
            ks[r][c4 + 2] = f.z; ks[r][c4 + 3] = f.w;
        }
        __syncthreads();
        #pragma unroll 16
        for (int kk = 0; kk < 64; kk++) {
            float vv = ks[kk][d];
            o0 += sc[qi0    ][kt + kk] * vv;
            o1 += sc[qi0 + 4][kt + kk] * vv;
        }
        __syncthreads();
    }
    out[((size_t)(b * TGT + qbase + qi0    )) * D_MODEL + h * DKH + d] = o0;
    out[((size_t)(b * TGT + qbase + qi0 + 4)) * D_MODEL + h * DKH + d] = o1;
}

// ---------------- add + LayerNorm (in place on x) --------------------------
// grid: ROWS_X blocks, 256 threads; row length D_MODEL=1024 (4 per thread)
__global__ __launch_bounds__(256)
void add_ln_kernel(float* __restrict__ x, const float* __restrict__ a,
                   const float* __restrict__ g, const float* __restrict__ bb) {
    __shared__ float scratch[8];
    __shared__ float mu_s, rstd_s;
    const int row = blockIdx.x, tid = threadIdx.x;
    float* xrow = x + (size_t)row * D_MODEL;
    const float* arow = a + (size_t)row * D_MODEL;

    float vals[4];
    float s = 0.f;
    #pragma unroll
    for (int i = 0; i < 4; i++) {
        int c = tid + i * 256;
        vals[i] = xrow[c] + arow[c];
        s += vals[i];
    }
    // reduce sum
    #pragma unroll
    for (int o = 16; o; o >>= 1) s += __shfl_xor_sync(~0u, s, o);
    if ((tid & 31) == 0) scratch[tid >> 5] = s;
    __syncthreads();
    if (tid == 0) {
        float t = 0.f;
        #pragma unroll
        for (int w = 0; w < 8; w++) t += scratch[w];
        mu_s = t * (1.f / D_MODEL);
    }
    __syncthreads();
    const float mu = mu_s;

    float vsum = 0.f;
    #pragma unroll
    for (int i = 0; i < 4; i++) {
        float d = vals[i] - mu;
        vsum += d * d;
    }
    #pragma unroll
    for (int o = 16; o; o >>= 1) vsum += __shfl_xor_sync(~0u, vsum, o);
    if ((tid & 31) == 0) scratch[tid >> 5] = vsum;
    __syncthreads();
    if (tid == 0) {
        float t = 0.f;
        #pragma unroll
        for (int w = 0; w < 8; w++) t += scratch[w];
        rstd_s = rsqrtf(t * (1.f / D_MODEL) + 1e-5f);
    }
    __syncthreads();
    const float r = rstd_s;

    #pragma unroll
    for (int i = 0; i < 4; i++) {
        int c = tid + i * 256;
        xrow[c] = (vals[i] - mu) * r * g[c] + bb[c];
    }
}

// ---------------- host orchestration ---------------------------------------
static inline dim3 gemm_grid(int M, int N) { return dim3(N / 128, M / 128); }

extern "C" void kernel_launch(void* const* d_in, const int* in_sizes, int n_in,
                              void* d_out, int out_size) {
    // ---- input binding -----------------------------------------------------
    // The harness passes inputs in metadata.txt order = setup_inputs() dict
    // insertion order:
    //   0 src, 1 tgt, 2 emb, 3 fc_w, 4 fc_b,
    //   5 sa_wq, 6 sa_bq, 7 sa_wk, 8 sa_bk, 9 sa_wv, 10 sa_bv, 11 sa_wo, 12 sa_bo,
    //   13 ca_wq, 14 ca_bq, 15 ca_wk, 16 ca_bk, 17 ca_wv, 18 ca_bv, 19 ca_wo, 20 ca_bo,
    //   21 w1, 22 b1, 23 w2, 24 b2,
    //   25 n1g, 26 n2g, 27 n3g, 28 n1b, 29 n2b, 30 n3b
    // Runtime disambiguation vs. reference-signature order: in_sizes[3] is
    // fc_w (D*V = 32,768,000) under dict order but sa_wq (L*D*D = 8,388,608)
    // under signature order.
    const float *src, *emb, *fc_w, *fc_b;
    const int* tgt;
    const float *sa_wq, *sa_bq, *sa_wk, *sa_bk, *sa_wv, *sa_bv, *sa_wo, *sa_bo;
    const float *ca_wq, *ca_bq, *ca_wk, *ca_bk, *ca_wv, *ca_bv, *ca_wo, *ca_bo;
    const float *w1, *b1, *w2, *b2;
    const float *n1g, *n1b, *n2g, *n2b, *n3g, *n3b;

    src = (const float*)d_in[0];
    tgt = (const int*)  d_in[1];
    emb = (const float*)d_in[2];

    if (in_sizes[3] == (int)((size_t)D_MODEL * VOCAB)) {
        // ---- dict insertion order (expected) ----
        fc_w  = (const float*)d_in[3];
        fc_b  = (const float*)d_in[4];
        sa_wq = (const float*)d_in[5];   sa_bq = (const float*)d_in[6];
        sa_wk = (const float*)d_in[7];   sa_bk = (const float*)d_in[8];
        sa_wv = (const float*)d_in[9];   sa_bv = (const float*)d_in[10];
        sa_wo = (const float*)d_in[11];  sa_bo = (const float*)d_in[12];
        ca_wq = (const float*)d_in[13];  ca_bq = (const float*)d_in[14];
        ca_wk = (const float*)d_in[15];  ca_bk = (const float*)d_in[16];
        ca_wv = (const float*)d_in[17];  ca_bv = (const float*)d_in[18];
        ca_wo = (const float*)d_in[19];  ca_bo = (const float*)d_in[20];
        w1    = (const float*)d_in[21];  b1    = (const float*)d_in[22];
        w2    = (const float*)d_in[23];  b2    = (const float*)d_in[24];
        n1g   = (const float*)d_in[25];
        n2g   = (const float*)d_in[26];
        n3g   = (const float*)d_in[27];
        n1b   = (const float*)d_in[28];
        n2b   = (const float*)d_in[29];
        n3b   = (const float*)d_in[30];
    } else {
        // ---- reference signature order (fallback) ----
        sa_wq = (const float*)d_in[3];   sa_bq = (const float*)d_in[4];
        sa_wk = (const float*)d_in[5];   sa_bk = (const float*)d_in[6];
        sa_wv = (const float*)d_in[7];   sa_bv = (const float*)d_in[8];
        sa_wo = (const float*)d_in[9];   sa_bo = (const float*)d_in[10];
        ca_wq = (const float*)d_in[11];  ca_bq = (const float*)d_in[12];
        ca_wk = (const float*)d_in[13];  ca_bk = (const float*)d_in[14];
        ca_wv = (const float*)d_in[15];  ca_bv = (const float*)d_in[16];
        ca_wo = (const float*)d_in[17];  ca_bo = (const float*)d_in[18];
        w1    = (const float*)d_in[19];  b1    = (const float*)d_in[20];
        w2    = (const float*)d_in[21];  b2    = (const float*)d_in[22];
        n1g   = (const float*)d_in[23];  n1b   = (const float*)d_in[24];
        n2g   = (const float*)d_in[25];  n2b   = (const float*)d_in[26];
        n3g   = (const float*)d_in[27];  n3b   = (const float*)d_in[28];
        fc_w  = (const float*)d_in[29];
        fc_b  = (const float*)d_in[30];
    }
    float* out = (float*)d_out;

    float *x, *enc, *q, *k, *v, *attn, *tmp, *ff;
    cudaGetSymbolAddress((void**)&x,    g_x);
    cudaGetSymbolAddress((void**)&enc,  g_enc);
    cudaGetSymbolAddress((void**)&q,    g_q);
    cudaGetSymbolAddress((void**)&k,    g_k);
    cudaGetSymbolAddress((void**)&v,    g_v);
    cudaGetSymbolAddress((void**)&attn, g_attn);
    cudaGetSymbolAddress((void**)&tmp,  g_tmp);
    cudaGetSymbolAddress((void**)&ff,   g_ff);

    embed_kernel<<<ROWS_X, 256>>>(tgt, emb, x);
    encpe_kernel<<<ROWS_E, 256>>>(src, enc);

    for (int l = 0; l < NLAYER; l++) {
        const size_t wo  = (size_t)l * D_MODEL * D_MODEL;
        const size_t bo  = (size_t)l * D_MODEL;
        const size_t w1o = (size_t)l * D_MODEL * FF_DIM;
        const size_t b1o = (size_t)l * FF_DIM;

        // ---- self attention ----
        sgemm_bias<false><<<gemm_grid(ROWS_X, D_MODEL), 256>>>(x, sa_wq + wo, sa_bq + bo, q, ROWS_X, D_MODEL, D_MODEL);
        sgemm_bias<false><<<gemm_grid(ROWS_X, D_MODEL), 256>>>(x, sa_wk + wo, sa_bk + bo, k, ROWS_X, D_MODEL, D_MODEL);
        sgemm_bias<false><<<gemm_grid(ROWS_X, D_MODEL), 256>>>(x, sa_wv + wo, sa_bv + bo, v, ROWS_X, D_MODEL, D_MODEL);
        attn_kernel<true><<<dim3(TGT / 8, NHEAD, BATCH), 256>>>(q, k, v, tgt, attn, TGT);
        sgemm_bias<false><<<gemm_grid(ROWS_X, D_MODEL), 256>>>(attn, sa_wo + wo, sa_bo + bo, tmp, ROWS_X, D_MODEL, D_MODEL);
        add_ln_kernel<<<ROWS_X, 256>>>(x, tmp, n1g + bo, n1b + bo);

        // ---- cross attention ----
        sgemm_bias<false><<<gemm_grid(ROWS_X, D_MODEL), 256>>>(x, ca_wq + wo, ca_bq + bo, q, ROWS_X, D_MODEL, D_MODEL);
        sgemm_bias<false><<<gemm_grid(ROWS_E, D_MODEL), 256>>>(enc, ca_wk + wo, ca_bk + bo, k, ROWS_E, D_MODEL, D_MODEL);
        sgemm_bias<false><<<gemm_grid(ROWS_E, D_MODEL), 256>>>(enc, ca_wv + wo, ca_bv + bo, v, ROWS_E, D_MODEL, D_MODEL);
        attn_kernel<false><<<dim3(TGT / 8, NHEAD, BATCH), 256>>>(q, k, v, nullptr, attn, SRCL);
        sgemm_bias<false><<<gemm_grid(ROWS_X, D_MODEL), 256>>>(attn, ca_wo + wo, ca_bo + bo, tmp, ROWS_X, D_MODEL, D_MODEL);
        add_ln_kernel<<<ROWS_X, 256>>>(x, tmp, n2g + bo, n2b + bo);

        // ---- feed forward ----
        sgemm_bias<true ><<<gemm_grid(ROWS_X, FF_DIM), 256>>>(x, w1 + w1o, b1 + b1o, ff, ROWS_X, FF_DIM, D_MODEL);
        sgemm_bias<false><<<gemm_grid(ROWS_X, D_MODEL), 256>>>(ff, w2 + w1o, b2 + bo, tmp, ROWS_X, D_MODEL, FF_DIM);
        add_ln_kernel<<<ROWS_X, 256>>>(x, tmp, n3g + bo, n3b + bo);
    }

    // ---- final projection to vocab ----
    sgemm_bias<false><<<gemm_grid(ROWS_X, VOCAB), 256>>>(x, fc_w, fc_b, out, ROWS_X, VOCAB, D_MODEL);
}

// round 15
// speedup vs baseline: 1.9033x; 1.9033x over previous
#include <cuda_runtime.h>
#include <cuda_bf16.h>
#include <math.h>
#include <stdint.h>

#define D_MODEL 1024
#define NHEAD   16
#define DKH     64
#define NLAYER  8
#define FF_DIM  4096
#define BATCH   4
#define TGT     512
#define SRCL    256
#define VOCAB   32000
#define ROWS_X  (BATCH*TGT)
#define ROWS_E  (BATCH*SRCL)

// ---------------- scratch ----------------
__device__ float g_x   [ROWS_X*(size_t)D_MODEL];
__device__ float g_enc [ROWS_E*(size_t)D_MODEL];
__device__ float g_q   [ROWS_X*(size_t)D_MODEL];
__device__ float g_k   [ROWS_X*(size_t)D_MODEL];
__device__ float g_v   [ROWS_X*(size_t)D_MODEL];
__device__ float g_attn[ROWS_X*(size_t)D_MODEL];
__device__ float g_tmp [ROWS_X*(size_t)D_MODEL];
__device__ float g_ff  [ROWS_X*(size_t)FF_DIM];

// bf16 hi/lo weights, transposed to [N][K]
#define ATTN_T_STRIDE 8388608ULL
#define ATTN_L_STRIDE 1048576ULL
#define W1_OFF  67108864ULL
#define W2_OFF  100663296ULL
#define FC_OFF  134217728ULL
#define WTOTAL  166985728ULL
__device__ __nv_bfloat16 g_whi[WTOTAL];
__device__ __nv_bfloat16 g_wlo[WTOTAL];
__device__ __nv_bfloat16 g_ahi[ROWS_X*(size_t)FF_DIM];
__device__ __nv_bfloat16 g_alo[ROWS_X*(size_t)FF_DIM];
__device__ __nv_bfloat16 g_ehi[ROWS_E*(size_t)D_MODEL];
__device__ __nv_bfloat16 g_elo[ROWS_E*(size_t)D_MODEL];

// ================= prep kernels =================
__global__ void split_act(const float* __restrict__ in,
                          __nv_bfloat16* __restrict__ hi,
                          __nv_bfloat16* __restrict__ lo, int n4) {
    int i = blockIdx.x * 256 + threadIdx.x;
    if (i >= n4) return;
    float4 v = ((const float4*)in)[i];
    __nv_bfloat16 h0 = __float2bfloat16(v.x), h1 = __float2bfloat16(v.y);
    __nv_bfloat16 h2 = __float2bfloat16(v.z), h3 = __float2bfloat16(v.w);
    __nv_bfloat162* hp = (__nv_bfloat162*)hi;
    __nv_bfloat162* lp = (__nv_bfloat162*)lo;
    __nv_bfloat162 a, b, c, d;
    a.x = h0; a.y = h1; b.x = h2; b.y = h3;
    c.x = __float2bfloat16(v.x - __bfloat162float(h0));
    c.y = __float2bfloat16(v.y - __bfloat162float(h1));
    d.x = __float2bfloat16(v.z - __bfloat162float(h2));
    d.y = __float2bfloat16(v.w - __bfloat162float(h3));
    hp[2*i] = a; hp[2*i+1] = b;
    lp[2*i] = c; lp[2*i+1] = d;
}

// W[K][N] fp32 -> hi/lo bf16 [N][K]
__global__ void transpose_split(const float* __restrict__ W,
                                __nv_bfloat16* __restrict__ hi,
                                __nv_bfloat16* __restrict__ lo, int K, int N) {
    __shared__ float t[32][33];
    int n0 = blockIdx.x * 32, k0 = blockIdx.y * 32;
    int tx = threadIdx.x, ty = threadIdx.y;   // (32,8)
    #pragma unroll
    for (int i = 0; i < 4; i++)
        t[ty + i*8][tx] = W[(size_t)(k0 + ty + i*8) * N + n0 + tx];
    __syncthreads();
    #pragma unroll
    for (int i = 0; i < 4; i++) {
        int n = n0 + ty + i*8, kk = k0 + tx;
        float v = t[tx][ty + i*8];
        __nv_bfloat16 h = __float2bfloat16(v);
        hi[(size_t)n * K + kk] = h;
        lo[(size_t)n * K + kk] = __float2bfloat16(v - __bfloat162float(h));
    }
}

// ================= mma.sync bf16 GEMM =================
// C[M,N] = A[M,K] @ W[K,N] + bias; A hi/lo [M][K] K-major, B hi/lo [N][K]
// K-major ([N][K] rows == col-major KxN => "row.col" mma). bf16x3 passes.
__device__ __forceinline__ void mma16816(float* c, const uint32_t* a, const uint32_t* b) {
    asm volatile(
        "mma.sync.aligned.m16n8k16.row.col.f32.bf16.bf16.f32 "
        "{%0,%1,%2,%3}, {%4,%5,%6,%7}, {%8,%9}, {%0,%1,%2,%3};"
        : "+f"(c[0]), "+f"(c[1]), "+f"(c[2]), "+f"(c[3])
        : "r"(a[0]), "r"(a[1]), "r"(a[2]), "r"(a[3]), "r"(b[0]), "r"(b[1]));
}

#define BM 128
#define BN 64
#define BK 32
#define ASTR 40   // smem row stride in halves -> conflict-free fragment LDS

template<bool RELU>
__global__ __launch_bounds__(256)
void gemm_mma(const __nv_bfloat16* __restrict__ Ahi, const __nv_bfloat16* __restrict__ Alo,
              const __nv_bfloat16* __restrict__ Bhi, const __nv_bfloat16* __restrict__ Blo,
              const float* __restrict__ bias, float* __restrict__ C,
              int M, int N, int K) {
    __shared__ __nv_bfloat16 sAh[BM][ASTR], sAl[BM][ASTR];
    __shared__ __nv_bfloat16 sBh[BN][ASTR], sBl[BN][ASTR];

    const int tid = threadIdx.x;
    const int wid = tid >> 5, lane = tid & 31;
    const int g = lane >> 2, t = lane & 3;
    const int wm = (wid >> 1) * 32, wn = (wid & 1) * 32;
    const int bm = blockIdx.y * BM, bn = blockIdx.x * BN;

    float acc[2][4][4];
    #pragma unroll
    for (int i = 0; i < 2; i++)
        #pragma unroll
        for (int j = 0; j < 4; j++)
            #pragma unroll
            for (int e = 0; e < 4; e++) acc[i][j][e] = 0.f;

    for (int kc = 0; kc < K; kc += BK) {
        // ---- fill smem ----
        #pragma unroll
        for (int i = tid; i < 512; i += 256) {     // A: 128 rows x 4 uint4
            int row = i >> 2, q = i & 3;
            const size_t off = (size_t)(bm + row) * K + kc + q * 8;
            *(uint4*)&sAh[row][q*8] = *(const uint4*)(Ahi + off);
            *(uint4*)&sAl[row][q*8] = *(const uint4*)(Alo + off);
        }
        {
            int i = tid;
            if (i < 256) {                          // B: 64 rows x 4 uint4
                int row = i >> 2, q = i & 3;
                const size_t off = (size_t)(bn + row) * K + kc + q * 8;
                *(uint4*)&sBh[row][q*8] = *(const uint4*)(Bhi + off);
                *(uint4*)&sBl[row][q*8] = *(const uint4*)(Blo + off);
            }
        }
        __syncthreads();

        #pragma unroll
        for (int ks = 0; ks < 2; ks++) {
            const int kb = ks * 16;
            uint32_t ah[2][4], al[2][4], bh[4][2], bl[4][2];
            #pragma unroll
            for (int am = 0; am < 2; am++) {
                int r0 = wm + am * 16 + g;
                ah[am][0] = *(const uint32_t*)&sAh[r0    ][kb + t*2];
                ah[am][1] = *(const uint32_t*)&sAh[r0 + 8][kb + t*2];
                ah[am][2] = *(const uint32_t*)&sAh[r0    ][kb + t*2 + 8];
                ah[am][3] = *(const uint32_t*)&sAh[r0 + 8][kb + t*2 + 8];
                al[am][0] = *(const uint32_t*)&sAl[r0    ][kb + t*2];
                al[am][1] = *(const uint32_t*)&sAl[r0 + 8][kb + t*2];
                al[am][2] = *(const uint32_t*)&sAl[r0    ][kb + t*2 + 8];
                al[am][3] = *(const uint32_t*)&sAl[r0 + 8][kb + t*2 + 8];
            }
            #pragma unroll
            for (int nb = 0; nb < 4; nb++) {
                int c0 = wn + nb * 8 + g;
                bh[nb][0] = *(const uint32_t*)&sBh[c0][kb + t*2];
                bh[nb][1] = *(const uint32_t*)&sBh[c0][kb + t*2 + 8];
                bl[nb][0] = *(const uint32_t*)&sBl[c0][kb + t*2];
                bl[nb][1] = *(const uint32_t*)&sBl[c0][kb + t*2 + 8];
            }
            #pragma unroll
            for (int am = 0; am < 2; am++)
                #pragma unroll
                for (int nb = 0; nb < 4; nb++) {
                    mma16816(acc[am][nb], ah[am], bh[nb]);
                    mma16816(acc[am][nb], al[am], bh[nb]);
                    mma16816(acc[am][nb], ah[am], bl[nb]);
                }
        }
        __syncthreads();
    }

    // ---- epilogue ----
    #pragma unroll
    for (int am = 0; am < 2; am++)
        #pragma unroll
        for (int nb = 0; nb < 4; nb++) {
            int row = bm + wm + am * 16 + g;
            int col = bn + wn + nb * 8 + t * 2;
            float bx = bias[col], by = bias[col + 1];
            float2 v0, v1;
            v0.x = acc[am][nb][0] + bx; v0.y = acc[am][nb][1] + by;
            v1.x = acc[am][nb][2] + bx; v1.y = acc[am][nb][3] + by;
            if (RELU) {
                v0.x = fmaxf(v0.x, 0.f); v0.y = fmaxf(v0.y, 0.f);
                v1.x = fmaxf(v1.x, 0.f); v1.y = fmaxf(v1.y, 0.f);
            }
            *(float2*)(C + (size_t)row * N + col)       = v0;
            *(float2*)(C + (size_t)(row + 8) * N + col) = v1;
        }
}

// ================= PE / embed =================
__device__ __forceinline__ float pe_val(int pos, int c) {
    int i2 = c & ~1;
    float div = expf((float)i2 * (-9.210340371976184f / (float)D_MODEL));
    float ang = (float)pos * div;
    return (c & 1) ? cosf(ang) : sinf(ang);
}
__global__ void embed_kernel(const int* __restrict__ tgt, const float* __restrict__ emb,
                             float* __restrict__ x) {
    int row = blockIdx.x, t = row % TGT;
    const float* erow = emb + (size_t)tgt[row] * D_MODEL;
    float* xrow = x + (size_t)row * D_MODEL;
    for (int c = threadIdx.x; c < D_MODEL; c += blockDim.x)
        xrow[c] = erow[c] + pe_val(t, c);
}
__global__ void encpe_kernel(const float* __restrict__ src, float* __restrict__ enc) {
    int row = blockIdx.x, s = row % SRCL;
    const float* srow = src + (size_t)row * D_MODEL;
    float* erow = enc + (size_t)row * D_MODEL;
    for (int c = threadIdx.x; c < D_MODEL; c += blockDim.x)
        erow[c] = srow[c] + pe_val(s, c);
}

// ================= attention (fp32) =================
template<bool MASKED>
__global__ __launch_bounds__(256)
void attn_kernel(const float* __restrict__ q, const float* __restrict__ k,
                 const float* __restrict__ v, const int* __restrict__ tgt,
                 float* __restrict__ out, int Skv) {
    const int qt = blockIdx.x, h = blockIdx.y, b = blockIdx.z;
    const int qbase = qt * 8, tid = threadIdx.x;

    __shared__ float qs[8][DKH];
    __shared__ float ks[64][65];
    __shared__ float sc[8][TGT];
    __shared__ int   rowok[8];

    for (int i = tid; i < 8 * DKH; i += 256) {
        int qi = i >> 6, d = i & 63;
        qs[qi][d] = q[((size_t)(b * TGT + qbase + qi)) * D_MODEL + h * DKH + d];
    }
    if (MASKED && tid < 8)
        rowok[tid] = (tgt[b * TGT + qbase + tid] != 0);
    __syncthreads();

    const int qi0 = tid >> 6, kj = tid & 63;

    for (int kt = 0; kt < Skv; kt += 64) {
        for (int i = tid; i < 64 * 16; i += 256) {
            int r = i >> 4, c4 = (i & 15) * 4;
            float4 f = *(const float4*)&k[((size_t)(b * Skv + kt + r)) * D_MODEL + h * DKH + c4];
            ks[r][c4+0] = f.x; ks[r][c4+1] = f.y; ks[r][c4+2] = f.z; ks[r][c4+3] = f.w;
        }
        __syncthreads();
        {
            float a0 = 0.f, a1 = 0.f;
            #pragma unroll
            for (int d = 0; d < DKH; d++) {
                float kv = ks[kj][d];
                a0 += qs[qi0][d] * kv;
                a1 += qs[qi0 + 4][d] * kv;
            }
            a0 *= 0.125f; a1 *= 0.125f;
            int kglob = kt + kj;
            if (MASKED) {
                if (!((kglob <= qbase + qi0)     && rowok[qi0]))     a0 = -1e9f;
                if (!((kglob <= qbase + qi0 + 4) && rowok[qi0 + 4])) a1 = -1e9f;
            }
            sc[qi0][kglob]     = a0;
            sc[qi0 + 4][kglob] = a1;
        }
        __syncthreads();
    }

    {
        int w = tid >> 5, lane = tid & 31;
        float m = -INFINITY;
        for (int j = lane; j < Skv; j += 32) m = fmaxf(m, sc[w][j]);
        #pragma unroll
        for (int o = 16; o; o >>= 1) m = fmaxf(m, __shfl_xor_sync(~0u, m, o));
        float ssum = 0.f;
        for (int j = lane; j < Skv; j += 32) {
            float e = __expf(sc[w][j] - m);
            sc[w][j] = e; ssum += e;
        }
        #pragma unroll
        for (int o = 16; o; o >>= 1) ssum += __shfl_xor_sync(~0u, ssum, o);
        float inv = 1.f / ssum;
        for (int j = lane; j < Skv; j += 32) sc[w][j] *= inv;
    }
    __syncthreads();

    const int d = tid & 63;
    float o0 = 0.f, o1 = 0.f;
    for (int kt = 0; kt < Skv; kt += 64) {
        for (int i = tid; i < 64 * 16; i += 256) {
            int r = i >> 4, c4 = (i & 15) * 4;
            float4 f = *(const float4*)&v[((size_t)(b * Skv + kt + r)) * D_MODEL + h * DKH + c4];
            ks[r][c4+0] = f.x; ks[r][c4+1] = f.y; ks[r][c4+2] = f.z; ks[r][c4+3] = f.w;
        }
        __syncthreads();
        #pragma unroll 16
        for (int kk = 0; kk < 64; kk++) {
            float vv = ks[kk][d];
            o0 += sc[qi0    ][kt + kk] * vv;
            o1 += sc[qi0 + 4][kt + kk] * vv;
        }
        __syncthreads();
    }
    out[((size_t)(b * TGT + qbase + qi0    )) * D_MODEL + h * DKH + d] = o0;
    out[((size_t)(b * TGT + qbase + qi0 + 4)) * D_MODEL + h * DKH + d] = o1;
}

// ================= add + LayerNorm =================
__global__ __launch_bounds__(256)
void add_ln_kernel(float* __restrict__ x, const float* __restrict__ a,
                   const float* __restrict__ g, const float* __restrict__ bb) {
    __shared__ float scratch[8];
    __shared__ float mu_s, rstd_s;
    const int row = blockIdx.x, tid = threadIdx.x;
    float* xrow = x + (size_t)row * D_MODEL;
    const float* arow = a + (size_t)row * D_MODEL;

    float vals[4]; float s = 0.f;
    #pragma unroll
    for (int i = 0; i < 4; i++) {
        int c = tid + i * 256;
        vals[i] = xrow[c] + arow[c];
        s += vals[i];
    }
    #pragma unroll
    for (int o = 16; o; o >>= 1) s += __shfl_xor_sync(~0u, s, o);
    if ((tid & 31) == 0) scratch[tid >> 5] = s;
    __syncthreads();
    if (tid == 0) {
        float t = 0.f;
        #pragma unroll
        for (int w = 0; w < 8; w++) t += scratch[w];
        mu_s = t * (1.f / D_MODEL);
    }
    __syncthreads();
    const float mu = mu_s;
    float vsum = 0.f;
    #pragma unroll
    for (int i = 0; i < 4; i++) { float dd = vals[i] - mu; vsum += dd * dd; }
    #pragma unroll
    for (int o = 16; o; o >>= 1) vsum += __shfl_xor_sync(~0u, vsum, o);
    if ((tid & 31) == 0) scratch[tid >> 5] = vsum;
    __syncthreads();
    if (tid == 0) {
        float t = 0.f;
        #pragma unroll
        for (int w = 0; w < 8; w++) t += scratch[w];
        rstd_s = rsqrtf(t * (1.f / D_MODEL) + 1e-5f);
    }
    __syncthreads();
    const float r = rstd_s;
    #pragma unroll
    for (int i = 0; i < 4; i++) {
        int c = tid + i * 256;
        xrow[c] = (vals[i] - mu) * r * g[c] + bb[c];
    }
}

// ================= host =================
static inline void launch_split(const float* in, __nv_bfloat16* hi,
                                __nv_bfloat16* lo, size_t n) {
    int n4 = (int)(n / 4);
    split_act<<<(n4 + 255) / 256, 256>>>(in, hi, lo, n4);
}
template<bool RELU>
static inline void launch_gemm(const __nv_bfloat16* ahi, const __nv_bfloat16* alo,
                               const __nv_bfloat16* bhi, const __nv_bfloat16* blo,
                               const float* bias, float* C, int M, int N, int K) {
    gemm_mma<RELU><<<dim3(N / BN, M / BM), 256>>>(ahi, alo, bhi, blo, bias, C, M, N, K);
}

extern "C" void kernel_launch(void* const* d_in, const int* in_sizes, int n_in,
                              void* d_out, int out_size) {
    const float *src, *emb, *fc_w, *fc_b;
    const int* tgt;
    const float *sa_wq, *sa_bq, *sa_wk, *sa_bk, *sa_wv, *sa_bv, *sa_wo, *sa_bo;
    const float *ca_wq, *ca_bq, *ca_wk, *ca_bk, *ca_wv, *ca_bv, *ca_wo, *ca_bo;
    const float *w1, *b1, *w2, *b2;
    const float *n1g, *n1b, *n2g, *n2b, *n3g, *n3b;

    src = (const float*)d_in[0];
    tgt = (const int*)  d_in[1];
    emb = (const float*)d_in[2];
    if (in_sizes[3] == (int)((size_t)D_MODEL * VOCAB)) {
        fc_w  = (const float*)d_in[3];   fc_b  = (const float*)d_in[4];
        sa_wq = (const float*)d_in[5];   sa_bq = (const float*)d_in[6];
        sa_wk = (const float*)d_in[7];   sa_bk = (const float*)d_in[8];
        sa_wv = (const float*)d_in[9];   sa_bv = (const float*)d_in[10];
        sa_wo = (const float*)d_in[11];  sa_bo = (const float*)d_in[12];
        ca_wq = (const float*)d_in[13];  ca_bq = (const float*)d_in[14];
        ca_wk = (const float*)d_in[15];  ca_bk = (const float*)d_in[16];
        ca_wv = (const float*)d_in[17];  ca_bv = (const float*)d_in[18];
        ca_wo = (const float*)d_in[19];  ca_bo = (const float*)d_in[20];
        w1    = (const float*)d_in[21];  b1    = (const float*)d_in[22];
        w2    = (const float*)d_in[23];  b2    = (const float*)d_in[24];
        n1g   = (const float*)d_in[25];  n2g   = (const float*)d_in[26];
        n3g   = (const float*)d_in[27];  n1b   = (const float*)d_in[28];
        n2b   = (const float*)d_in[29];  n3b   = (const float*)d_in[30];
    } else {
        sa_wq = (const float*)d_in[3];   sa_bq = (const float*)d_in[4];
        sa_wk = (const float*)d_in[5];   sa_bk = (const float*)d_in[6];
        sa_wv = (const float*)d_in[7];   sa_bv = (const float*)d_in[8];
        sa_wo = (const float*)d_in[9];   sa_bo = (const float*)d_in[10];
        ca_wq = (const float*)d_in[11];  ca_bq = (const float*)d_in[12];
        ca_wk = (const float*)d_in[13];  ca_bk = (const float*)d_in[14];
        ca_wv = (const float*)d_in[15];  ca_bv = (const float*)d_in[16];
        ca_wo = (const float*)d_in[17];  ca_bo = (const float*)d_in[18];
        w1    = (const float*)d_in[19];  b1    = (const float*)d_in[20];
        w2    = (const float*)d_in[21];  b2    = (const float*)d_in[22];
        n1g   = (const float*)d_in[23];  n1b   = (const float*)d_in[24];
        n2g   = (const float*)d_in[25];  n2b   = (const float*)d_in[26];
        n3g   = (const float*)d_in[27];  n3b   = (const float*)d_in[28];
        fc_w  = (const float*)d_in[29];  fc_b  = (const float*)d_in[30];
    }
    float* out = (float*)d_out;

    float *x, *enc, *q, *k, *v, *attn, *tmp, *ff;
    cudaGetSymbolAddress((void**)&x,    g_x);
    cudaGetSymbolAddress((void**)&enc,  g_enc);
    cudaGetSymbolAddress((void**)&q,    g_q);
    cudaGetSymbolAddress((void**)&k,    g_k);
    cudaGetSymbolAddress((void**)&v,    g_v);
    cudaGetSymbolAddress((void**)&attn, g_attn);
    cudaGetSymbolAddress((void**)&tmp,  g_tmp);
    cudaGetSymbolAddress((void**)&ff,   g_ff);

    __nv_bfloat16 *whi, *wlo, *ahi, *alo, *ehi, *elo;
    cudaGetSymbolAddress((void**)&whi, g_whi);
    cudaGetSymbolAddress((void**)&wlo, g_wlo);
    cudaGetSymbolAddress((void**)&ahi, g_ahi);
    cudaGetSymbolAddress((void**)&alo, g_alo);
    cudaGetSymbolAddress((void**)&ehi, g_ehi);
    cudaGetSymbolAddress((void**)&elo, g_elo);

    // ---- weight prep: transpose + hi/lo split into [N][K] bf16 ----
    {
        const float* attn_w[8] = {sa_wq, sa_wk, sa_wv, sa_wo, ca_wq, ca_wk, ca_wv, ca_wo};
        dim3 thr(32, 8);
        for (int t = 0; t < 8; t++)
            for (int l = 0; l < NLAYER; l++) {
                size_t off = (size_t)t * ATTN_T_STRIDE + (size_t)l * ATTN_L_STRIDE;
                transpose_split<<<dim3(32, 32), thr>>>(
                    attn_w[t] + (size_t)l * D_MODEL * D_MODEL,
                    whi + off, wlo + off, D_MODEL, D_MODEL);
            }
        for (int l = 0; l < NLAYER; l++) {
            size_t off = W1_OFF + (size_t)l * 4194304ULL;
            transpose_split<<<dim3(FF_DIM/32, D_MODEL/32), thr>>>(
                w1 + (size_t)l * D_MODEL * FF_DIM, whi + off, wlo + off, D_MODEL, FF_DIM);
            off = W2_OFF + (size_t)l * 4194304ULL;
            transpose_split<<<dim3(D_MODEL/32, FF_DIM/32), thr>>>(
                w2 + (size_t)l * FF_DIM * D_MODEL, whi + off, wlo + off, FF_DIM, D_MODEL);
        }
        transpose_split<<<dim3(VOCAB/32, D_MODEL/32), thr>>>(
            fc_w, whi + FC_OFF, wlo + FC_OFF, D_MODEL, VOCAB);
    }

    embed_kernel<<<ROWS_X, 256>>>(tgt, emb, x);
    encpe_kernel<<<ROWS_E, 256>>>(src, enc);
    launch_split(enc, ehi, elo, (size_t)ROWS_E * D_MODEL);

    for (int l = 0; l < NLAYER; l++) {
        const size_t bo  = (size_t)l * D_MODEL;
        const size_t b1o = (size_t)l * FF_DIM;
        const size_t wA  = (size_t)l * ATTN_L_STRIDE;
        #define WT(t) (whi + (size_t)(t) * ATTN_T_STRIDE + wA), (wlo + (size_t)(t) * ATTN_T_STRIDE + wA)

        // ---- self attention ----
        launch_split(x, ahi, alo, (size_t)ROWS_X * D_MODEL);
        launch_gemm<false>(ahi, alo, WT(0), sa_bq + bo, q, ROWS_X, D_MODEL, D_MODEL);
        launch_gemm<false>(ahi, alo, WT(1), sa_bk + bo, k, ROWS_X, D_MODEL, D_MODEL);
        launch_gemm<false>(ahi, alo, WT(2), sa_bv + bo, v, ROWS_X, D_MODEL, D_MODEL);
        attn_kernel<true><<<dim3(TGT / 8, NHEAD, BATCH), 256>>>(q, k, v, tgt, attn, TGT);
        launch_split(attn, ahi, alo, (size_t)ROWS_X * D_MODEL);
        launch_gemm<false>(ahi, alo, WT(3), sa_bo + bo, tmp, ROWS_X, D_MODEL, D_MODEL);
        add_ln_kernel<<<ROWS_X, 256>>>(x, tmp, n1g + bo, n1b + bo);

        // ---- cross attention ----
        launch_split(x, ahi, alo, (size_t)ROWS_X * D_MODEL);
        launch_gemm<false>(ahi, alo, WT(4), ca_bq + bo, q, ROWS_X, D_MODEL, D_MODEL);
        launch_gemm<false>(ehi, elo, WT(5), ca_bk + bo, k, ROWS_E, D_MODEL, D_MODEL);
        launch_gemm<false>(ehi, elo, WT(6), ca_bv + bo, v, ROWS_E, D_MODEL, D_MODEL);
        attn_kernel<false><<<dim3(TGT / 8, NHEAD, BATCH), 256>>>(q, k, v, nullptr, attn, SRCL);
        launch_split(attn, ahi, alo, (size_t)ROWS_X * D_MODEL);
        launch_gemm<false>(ahi, alo, WT(7), ca_bo + bo, tmp, ROWS_X, D_MODEL, D_MODEL);
        add_ln_kernel<<<ROWS_X, 256>>>(x, tmp, n2g + bo, n2b + bo);

        // ---- feed forward ----
        launch_split(x, ahi, alo, (size_t)ROWS_X * D_MODEL);
        launch_gemm<true>(ahi, alo, whi + W1_OFF + (size_t)l * 4194304ULL,
                          wlo + W1_OFF + (size_t)l * 4194304ULL,
                          b1 + b1o, ff, ROWS_X, FF_DIM, D_MODEL);
        launch_split(ff, ahi, alo, (size_t)ROWS_X * FF_DIM);
        launch_gemm<false>(ahi, alo, whi + W2_OFF + (size_t)l * 4194304ULL,
                           wlo + W2_OFF + (size_t)l * 4194304ULL,
                           b2 + bo, tmp, ROWS_X, D_MODEL, FF_DIM);
        add_ln_kernel<<<ROWS_X, 256>>>(x, tmp, n3g + bo, n3b + bo);
        #undef WT
    }

    // ---- final projection to vocab ----
    launch_split(x, ahi, alo, (size_t)ROWS_X * D_MODEL);
    launch_gemm<false>(ahi, alo, whi + FC_OFF, wlo + FC_OFF, fc_b, out,
                       ROWS_X, VOCAB, D_MODEL);
}

// round 17
// speedup vs baseline: 2.1490x; 1.1291x over previous
#include <cuda_runtime.h>
#include <cuda_bf16.h>
#include <math.h>
#include <stdint.h>

#define D_MODEL 1024
#define NHEAD   16
#define DKH     64
#define NLAYER  8
#define FF_DIM  4096
#define BATCH   4
#define TGT     512
#define SRCL    256
#define VOCAB   32000
#define ROWS_X  (BATCH*TGT)
#define ROWS_E  (BATCH*SRCL)

// ---------------- scratch ----------------
__device__ float g_x   [ROWS_X*(size_t)D_MODEL];
__device__ float g_enc [ROWS_E*(size_t)D_MODEL];
__device__ float g_q   [ROWS_X*(size_t)D_MODEL];
__device__ float g_k   [ROWS_X*(size_t)D_MODEL];
__device__ float g_v   [ROWS_X*(size_t)D_MODEL];
__device__ float g_tmp [ROWS_X*(size_t)D_MODEL];

// bf16 hi/lo weights, transposed to [N][K]
#define ATTN_T_STRIDE 8388608ULL
#define ATTN_L_STRIDE 1048576ULL
#define W1_OFF  67108864ULL
#define W2_OFF  100663296ULL
#define FC_OFF  134217728ULL
#define WTOTAL  166985728ULL
__device__ __nv_bfloat16 g_whi[WTOTAL];
__device__ __nv_bfloat16 g_wlo[WTOTAL];
// activation hi/lo buffers
__device__ __nv_bfloat16 g_xhi[ROWS_X*(size_t)D_MODEL];
__device__ __nv_bfloat16 g_xlo[ROWS_X*(size_t)D_MODEL];
__device__ __nv_bfloat16 g_athi[ROWS_X*(size_t)D_MODEL];
__device__ __nv_bfloat16 g_atlo[ROWS_X*(size_t)D_MODEL];
__device__ __nv_bfloat16 g_ffhi[ROWS_X*(size_t)FF_DIM];
__device__ __nv_bfloat16 g_fflo[ROWS_X*(size_t)FF_DIM];
__device__ __nv_bfloat16 g_ehi[ROWS_E*(size_t)D_MODEL];
__device__ __nv_bfloat16 g_elo[ROWS_E*(size_t)D_MODEL];

__device__ __forceinline__ uint32_t smem_u32(const void* p) {
    uint32_t a;
    asm("{ .reg .u64 t; cvta.to.shared.u64 t, %1; cvt.u32.u64 %0, t; }" : "=r"(a) : "l"(p));
    return a;
}
__device__ __forceinline__ void split2(float v, __nv_bfloat16& h, __nv_bfloat16& l) {
    h = __float2bfloat16(v);
    l = __float2bfloat16(v - __bfloat162float(h));
}

// ================= prep kernels =================
__global__ void split_act(const float* __restrict__ in,
                          __nv_bfloat16* __restrict__ hi,
                          __nv_bfloat16* __restrict__ lo, int n) {
    int i = blockIdx.x * 256 + threadIdx.x;
    if (i >= n) return;
    __nv_bfloat16 h, l;
    split2(in[i], h, l);
    hi[i] = h; lo[i] = l;
}

// W[K][N] fp32 -> hi/lo bf16 [N][K]
__global__ void transpose_split(const float* __restrict__ W,
                                __nv_bfloat16* __restrict__ hi,
                                __nv_bfloat16* __restrict__ lo, int K, int N) {
    __shared__ float t[32][33];
    int n0 = blockIdx.x * 32, k0 = blockIdx.y * 32;
    int tx = threadIdx.x, ty = threadIdx.y;   // (32,8)
    #pragma unroll
    for (int i = 0; i < 4; i++)
        t[ty + i*8][tx] = W[(size_t)(k0 + ty + i*8) * N + n0 + tx];
    __syncthreads();
    #pragma unroll
    for (int i = 0; i < 4; i++) {
        int n = n0 + ty + i*8, kk = k0 + tx;
        __nv_bfloat16 h, l;
        split2(t[tx][ty + i*8], h, l);
        hi[(size_t)n * K + kk] = h;
        lo[(size_t)n * K + kk] = l;
    }
}

// ================= mma.sync bf16 GEMM (ldmatrix + cp.async) =================
__device__ __forceinline__ void mma16816(float* c, const uint32_t* a, const uint32_t* b) {
    asm volatile(
        "mma.sync.aligned.m16n8k16.row.col.f32.bf16.bf16.f32 "
        "{%0,%1,%2,%3}, {%4,%5,%6,%7}, {%8,%9}, {%0,%1,%2,%3};"
        : "+f"(c[0]), "+f"(c[1]), "+f"(c[2]), "+f"(c[3])
        : "r"(a[0]), "r"(a[1]), "r"(a[2]), "r"(a[3]), "r"(b[0]), "r"(b[1]));
}
#define LDSM_X4(r0, r1, r2, r3, addr) \
    asm volatile("ldmatrix.sync.aligned.m8n8.x4.shared.b16 {%0,%1,%2,%3}, [%4];" \
        : "=r"(r0), "=r"(r1), "=r"(r2), "=r"(r3) : "r"(addr))
#define CP16(dst, src) \
    asm volatile("cp.async.cg.shared.global [%0], [%1], 16;" :: "r"(dst), "l"(src))
#define CP_COMMIT()  asm volatile("cp.async.commit_group;" ::: "memory")
#define CP_WAIT(n)   asm volatile("cp.async.wait_group %0;" :: "n"(n) : "memory")

#define BM 128
#define BN 64
#define BK 32
#define ASTR 40                 // halves per smem row (80B) -> LDSM conflict-free
#define OFF_AH 0
#define OFF_AL 10240
#define OFF_BH 20480
#define OFF_BL 25600
#define STAGE  30720
#define GSMEM  (2*STAGE)

template<bool RELU, bool SPLIT>
__global__ __launch_bounds__(256)
void gemm_mma(const __nv_bfloat16* __restrict__ Ahi, const __nv_bfloat16* __restrict__ Alo,
              const __nv_bfloat16* __restrict__ Bhi, const __nv_bfloat16* __restrict__ Blo,
              const float* __restrict__ bias, float* __restrict__ C,
              __nv_bfloat16* __restrict__ Chi, __nv_bfloat16* __restrict__ Clo,
              int M, int N, int K) {
    extern __shared__ char smem[];
    const uint32_t sbase = smem_u32(smem);
    const int tid = threadIdx.x;
    const int wid = tid >> 5, lane = tid & 31;
    const int g = lane >> 2, t = lane & 3;
    const int wm = (wid >> 1) * 32, wn = (wid & 1) * 32;
    const int bm = blockIdx.y * BM, bn = blockIdx.x * BN;

    // ldmatrix per-lane byte offsets within a stage
    const uint32_t a_off = (uint32_t)(((wm + (lane & 15)) * ASTR + ((lane & 16) ? 8 : 0)) * 2);
    const uint32_t b_off = (uint32_t)(((wn + (lane & 7) + ((lane & 16) ? 8 : 0)) * ASTR
                                       + ((lane & 8) ? 8 : 0)) * 2);
    // cp.async indices
    const int arow0 = tid >> 2, aq = tid & 3;          // rows 0..63
    const int arow1 = arow0 + 64;                      // rows 64..127

    float acc[2][4][4];
    #pragma unroll
    for (int i = 0; i < 2; i++)
        #pragma unroll
        for (int j = 0; j < 4; j++)
            #pragma unroll
            for (int e = 0; e < 4; e++) acc[i][j][e] = 0.f;

    auto fill = [&](int c, int s) {
        const int kc = c * BK;
        const uint32_t st = sbase + s * STAGE;
        {
            const size_t off0 = (size_t)(bm + arow0) * K + kc + aq * 8;
            const size_t off1 = (size_t)(bm + arow1) * K + kc + aq * 8;
            uint32_t d0 = st + OFF_AH + (uint32_t)((arow0 * ASTR + aq * 8) * 2);
            uint32_t d1 = st + OFF_AH + (uint32_t)((arow1 * ASTR + aq * 8) * 2);
            CP16(d0,                      (const void*)(Ahi + off0));
            CP16(d0 + (OFF_AL - OFF_AH),  (const void*)(Alo + off0));
            CP16(d1,                      (const void*)(Ahi + off1));
            CP16(d1 + (OFF_AL - OFF_AH),  (const void*)(Alo + off1));
        }
        if (arow0 < 64) {   // tid < 256 always true; rows 0..63 for B
            const size_t off = (size_t)(bn + arow0) * K + kc + aq * 8;
            uint32_t d = st + OFF_BH + (uint32_t)((arow0 * ASTR + aq * 8) * 2);
            CP16(d,                      (const void*)(Bhi + off));
            CP16(d + (OFF_BL - OFF_BH),  (const void*)(Blo + off));
        }
    };

    const int nchunks = K / BK;
    fill(0, 0);
    CP_COMMIT();

    for (int c = 0; c < nchunks; c++) {
        const int s = c & 1;
        if (c + 1 < nchunks) {
            fill(c + 1, (c + 1) & 1);
            CP_COMMIT();
            CP_WAIT(1);
        } else {
            CP_WAIT(0);
        }
        __syncthreads();

        const uint32_t st = sbase + s * STAGE;
        #pragma unroll
        for (int ks = 0; ks < 2; ks++) {
            const uint32_t kb = ks * 32;   // 16 halves = 32 bytes
            uint32_t ah[2][4], al[2][4], bh[8], bl[8];
            #pragma unroll
            for (int am = 0; am < 2; am++) {
                uint32_t adr = st + OFF_AH + a_off + am * (16 * ASTR * 2) + kb;
                LDSM_X4(ah[am][0], ah[am][1], ah[am][2], ah[am][3], adr);
                adr += (OFF_AL - OFF_AH);
                LDSM_X4(al[am][0], al[am][1], al[am][2], al[am][3], adr);
            }
            {
                uint32_t adr = st + OFF_BH + b_off + kb;
                LDSM_X4(bh[0], bh[1], bh[2], bh[3], adr);
                LDSM_X4(bh[4], bh[5], bh[6], bh[7], adr + 16 * ASTR * 2);
                adr += (OFF_BL - OFF_BH);
                LDSM_X4(bl[0], bl[1], bl[2], bl[3], adr);
                LDSM_X4(bl[4], bl[5], bl[6], bl[7], adr + 16 * ASTR * 2);
            }
            #pragma unroll
            for (int am = 0; am < 2; am++)
                #pragma unroll
                for (int nb = 0; nb < 4; nb++) {
                    mma16816(acc[am][nb], ah[am], &bh[nb * 2]);
                    mma16816(acc[am][nb], al[am], &bh[nb * 2]);
                    mma16816(acc[am][nb], ah[am], &bl[nb * 2]);
                }
        }
        __syncthreads();
    }

    // ---- epilogue ----
    #pragma unroll
    for (int am = 0; am < 2; am++)
        #pragma unroll
        for (int nb = 0; nb < 4; nb++) {
            int row = bm + wm + am * 16 + g;
            int col = bn + wn + nb * 8 + t * 2;
            float bx = bias[col], by = bias[col + 1];
            float v00 = acc[am][nb][0] + bx, v01 = acc[am][nb][1] + by;
            float v10 = acc[am][nb][2] + bx, v11 = acc[am][nb][3] + by;
            if (RELU) {
                v00 = fmaxf(v00, 0.f); v01 = fmaxf(v01, 0.f);
                v10 = fmaxf(v10, 0.f); v11 = fmaxf(v11, 0.f);
            }
            if (SPLIT) {
                __nv_bfloat162 h0, l0, h1, l1;
                split2(v00, h0.x, l0.x); split2(v01, h0.y, l0.y);
                split2(v10, h1.x, l1.x); split2(v11, h1.y, l1.y);
                *(__nv_bfloat162*)(Chi + (size_t)row * N + col)       = h0;
                *(__nv_bfloat162*)(Clo + (size_t)row * N + col)       = l0;
                *(__nv_bfloat162*)(Chi + (size_t)(row + 8) * N + col) = h1;
                *(__nv_bfloat162*)(Clo + (size_t)(row + 8) * N + col) = l1;
            } else {
                float2 v0; v0.x = v00; v0.y = v01;
                float2 v1; v1.x = v10; v1.y = v11;
                *(float2*)(C + (size_t)row * N + col)       = v0;
                *(float2*)(C + (size_t)(row + 8) * N + col) = v1;
            }
        }
}

// ================= PE / embed =================
__device__ __forceinline__ float pe_val(int pos, int c) {
    int i2 = c & ~1;
    float div = expf((float)i2 * (-9.210340371976184f / (float)D_MODEL));
    float ang = (float)pos * div;
    return (c & 1) ? cosf(ang) : sinf(ang);
}
__global__ void embed_kernel(const int* __restrict__ tgt, const float* __restrict__ emb,
                             float* __restrict__ x,
                             __nv_bfloat16* __restrict__ xhi,
                             __nv_bfloat16* __restrict__ xlo) {
    int row = blockIdx.x, t = row % TGT;
    const float* erow = emb + (size_t)tgt[row] * D_MODEL;
    size_t base = (size_t)row * D_MODEL;
    for (int c = threadIdx.x; c < D_MODEL; c += blockDim.x) {
        float v = erow[c] + pe_val(t, c);
        x[base + c] = v;
        __nv_bfloat16 h, l;
        split2(v, h, l);
        xhi[base + c] = h; xlo[base + c] = l;
    }
}
__global__ void encpe_kernel(const float* __restrict__ src, float* __restrict__ enc) {
    int row = blockIdx.x, s = row % SRCL;
    const float* srow = src + (size_t)row * D_MODEL;
    float* erow = enc + (size_t)row * D_MODEL;
    for (int c = threadIdx.x; c < D_MODEL; c += blockDim.x)
        erow[c] = srow[c] + pe_val(s, c);
}

// ================= attention (fp32 in, bf16 hi/lo out) =================
template<bool MASKED>
__global__ __launch_bounds__(256)
void attn_kernel(const float* __restrict__ q, const float* __restrict__ k,
                 const float* __restrict__ v, const int* __restrict__ tgt,
                 __nv_bfloat16* __restrict__ ohi, __nv_bfloat16* __restrict__ olo,
                 int Skv) {
    const int qt = blockIdx.x, h = blockIdx.y, b = blockIdx.z;
    const int qbase = qt * 8, tid = threadIdx.x;

    __shared__ float qs[8][DKH];
    __shared__ float ks[64][65];
    __shared__ float sc[8][TGT];
    __shared__ int   rowok[8];

    for (int i = tid; i < 8 * DKH; i += 256) {
        int qi = i >> 6, d = i & 63;
        qs[qi][d] = q[((size_t)(b * TGT + qbase + qi)) * D_MODEL + h * DKH + d];
    }
    if (MASKED && tid < 8)
        rowok[tid] = (tgt[b * TGT + qbase + tid] != 0);
    __syncthreads();

    const int qi0 = tid >> 6, kj = tid & 63;

    for (int kt = 0; kt < Skv; kt += 64) {
        for (int i = tid; i < 64 * 16; i += 256) {
            int r = i >> 4, c4 = (i & 15) * 4;
            float4 f = *(const float4*)&k[((size_t)(b * Skv + kt + r)) * D_MODEL + h * DKH + c4];
            ks[r][c4+0] = f.x; ks[r][c4+1] = f.y; ks[r][c4+2] = f.z; ks[r][c4+3] = f.w;
        }
        __syncthreads();
        {
            float a0 = 0.f, a1 = 0.f;
            #pragma unroll
            for (int d = 0; d < DKH; d++) {
                float kv = ks[kj][d];
                a0 += qs[qi0][d] * kv;
                a1 += qs[qi0 + 4][d] * kv;
            }
            a0 *= 0.125f; a1 *= 0.125f;
            int kglob = kt + kj;
            if (MASKED) {
                if (!((kglob <= qbase + qi0)     && rowok[qi0]))     a0 = -1e9f;
                if (!((kglob <= qbase + qi0 + 4) && rowok[qi0 + 4])) a1 = -1e9f;
            }
            sc[qi0][kglob]     = a0;
            sc[qi0 + 4][kglob] = a1;
        }
        __syncthreads();
    }

    {
        int w = tid >> 5, lane = tid & 31;
        float m = -INFINITY;
        for (int j = lane; j < Skv; j += 32) m = fmaxf(m, sc[w][j]);
        #pragma unroll
        for (int o = 16; o; o >>= 1) m = fmaxf(m, __shfl_xor_sync(~0u, m, o));
        float ssum = 0.f;
        for (int j = lane; j < Skv; j += 32) {
            float e = __expf(sc[w][j] - m);
            sc[w][j] = e; ssum += e;
        }
        #pragma unroll
        for (int o = 16; o; o >>= 1) ssum += __shfl_xor_sync(~0u, ssum, o);
        float inv = 1.f / ssum;
        for (int j = lane; j < Skv; j += 32) sc[w][j] *= inv;
    }
    __syncthreads();

    const int d = tid & 63;
    float o0 = 0.f, o1 = 0.f;
    for (int kt = 0; kt < Skv; kt += 64) {
        for (int i = tid; i < 64 * 16; i += 256) {
            int r = i >> 4, c4 = (i & 15) * 4;
            float4 f = *(const float4*)&v[((size_t)(b * Skv + kt + r)) * D_MODEL + h * DKH + c4];
            ks[r][c4+0] = f.x; ks[r][c4+1] = f.y; ks[r][c4+2] = f.z; ks[r][c4+3] = f.w;
        }
        __syncthreads();
        #pragma unroll 16
        for (int kk = 0; kk < 64; kk++) {
            float vv = ks[kk][d];
            o0 += sc[qi0    ][kt + kk] * vv;
            o1 += sc[qi0 + 4][kt + kk] * vv;
        }
        __syncthreads();
    }
    {
        size_t i0 = ((size_t)(b * TGT + qbase + qi0    )) * D_MODEL + h * DKH + d;
        size_t i1 = ((size_t)(b * TGT + qbase + qi0 + 4)) * D_MODEL + h * DKH + d;
        __nv_bfloat16 h0, l0, h1, l1;
        split2(o0, h0, l0); split2(o1, h1, l1);
        ohi[i0] = h0; olo[i0] = l0;
        ohi[i1] = h1; olo[i1] = l1;
    }
}

// ================= add + LayerNorm (writes fp32 x and hi/lo) ==============
__global__ __launch_bounds__(256)
void add_ln_kernel(float* __restrict__ x, const float* __restrict__ a,
                   const float* __restrict__ g, const float* __restrict__ bb,
                   __nv_bfloat16* __restrict__ xhi, __nv_bfloat16* __restrict__ xlo) {
    __shared__ float scratch[8];
    __shared__ float mu_s, rstd_s;
    const int row = blockIdx.x, tid = threadIdx.x;
    float* xrow = x + (size_t)row * D_MODEL;
    const float* arow = a + (size_t)row * D_MODEL;

    float vals[4]; float s = 0.f;
    #pragma unroll
    for (int i = 0; i < 4; i++) {
        int c = tid + i * 256;
        vals[i] = xrow[c] + arow[c];
        s += vals[i];
    }
    #pragma unroll
    for (int o = 16; o; o >>= 1) s += __shfl_xor_sync(~0u, s, o);
    if ((tid & 31) == 0) scratch[tid >> 5] = s;
    __syncthreads();
    if (tid == 0) {
        float t = 0.f;
        #pragma unroll
        for (int w = 0; w < 8; w++) t += scratch[w];
        mu_s = t * (1.f / D_MODEL);
    }
    __syncthreads();
    const float mu = mu_s;
    float vsum = 0.f;
    #pragma unroll
    for (int i = 0; i < 4; i++) { float dd = vals[i] - mu; vsum += dd * dd; }
    #pragma unroll
    for (int o = 16; o; o >>= 1) vsum += __shfl_xor_sync(~0u, vsum, o);
    if ((tid & 31) == 0) scratch[tid >> 5] = vsum;
    __syncthreads();
    if (tid == 0) {
        float t = 0.f;
        #pragma unroll
        for (int w = 0; w < 8; w++) t += scratch[w];
        rstd_s = rsqrtf(t * (1.f / D_MODEL) + 1e-5f);
    }
    __syncthreads();
    const float r = rstd_s;
    #pragma unroll
    for (int i = 0; i < 4; i++) {
        int c = tid + i * 256;
        float v = (vals[i] - mu) * r * g[c] + bb[c];
        xrow[c] = v;
        __nv_bfloat16 h, l;
        split2(v, h, l);
        xhi[(size_t)row * D_MODEL + c] = h;
        xlo[(size_t)row * D_MODEL + c] = l;
    }
}

// ================= host =================
template<bool RELU, bool SPLIT>
static inline void launch_gemm(const __nv_bfloat16* ahi, const __nv_bfloat16* alo,
                               const __nv_bfloat16* bhi, const __nv_bfloat16* blo,
                               const float* bias, float* C,
                               __nv_bfloat16* Chi, __nv_bfloat16* Clo,
                               int M, int N, int K) {
    gemm_mma<RELU, SPLIT><<<dim3(N / BN, M / BM), 256, GSMEM>>>(
        ahi, alo, bhi, blo, bias, C, Chi, Clo, M, N, K);
}

extern "C" void kernel_launch(void* const* d_in, const int* in_sizes, int n_in,
                              void* d_out, int out_size) {
    const float *src, *emb, *fc_w, *fc_b;
    const int* tgt;
    const float *sa_wq, *sa_bq, *sa_wk, *sa_bk, *sa_wv, *sa_bv, *sa_wo, *sa_bo;
    const float *ca_wq, *ca_bq, *ca_wk, *ca_bk, *ca_wv, *ca_bv, *ca_wo, *ca_bo;
    const float *w1, *b1, *w2, *b2;
    const float *n1g, *n1b, *n2g, *n2b, *n3g, *n3b;

    src = (const float*)d_in[0];
    tgt = (const int*)  d_in[1];
    emb = (const float*)d_in[2];
    if (in_sizes[3] == (int)((size_t)D_MODEL * VOCAB)) {
        fc_w  = (const float*)d_in[3];   fc_b  = (const float*)d_in[4];
        sa_wq = (const float*)d_in[5];   sa_bq = (const float*)d_in[6];
        sa_wk = (const float*)d_in[7];   sa_bk = (const float*)d_in[8];
        sa_wv = (const float*)d_in[9];   sa_bv = (const float*)d_in[10];
        sa_wo = (const float*)d_in[11];  sa_bo = (const float*)d_in[12];
        ca_wq = (const float*)d_in[13];  ca_bq = (const float*)d_in[14];
        ca_wk = (const float*)d_in[15];  ca_bk = (const float*)d_in[16];
        ca_wv = (const float*)d_in[17];  ca_bv = (const float*)d_in[18];
        ca_wo = (const float*)d_in[19];  ca_bo = (const float*)d_in[20];
        w1    = (const float*)d_in[21];  b1    = (const float*)d_in[22];
        w2    = (const float*)d_in[23];  b2    = (const float*)d_in[24];
        n1g   = (const float*)d_in[25];  n2g   = (const float*)d_in[26];
        n3g   = (const float*)d_in[27];  n1b   = (const float*)d_in[28];
        n2b   = (const float*)d_in[29];  n3b   = (const float*)d_in[30];
    } else {
        sa_wq = (const float*)d_in[3];   sa_bq = (const float*)d_in[4];
        sa_wk = (const float*)d_in[5];   sa_bk = (const float*)d_in[6];
        sa_wv = (const float*)d_in[7];   sa_bv = (const float*)d_in[8];
        sa_wo = (const float*)d_in[9];   sa_bo = (const float*)d_in[10];
        ca_wq = (const float*)d_in[11];  ca_bq = (const float*)d_in[12];
        ca_wk = (const float*)d_in[13];  ca_bk = (const float*)d_in[14];
        ca_wv = (const float*)d_in[15];  ca_bv = (const float*)d_in[16];
        ca_wo = (const float*)d_in[17];  ca_bo = (const float*)d_in[18];
        w1    = (const float*)d_in[19];  b1    = (const float*)d_in[20];
        w2    = (const float*)d_in[21];  b2    = (const float*)d_in[22];
        n1g   = (const float*)d_in[23];  n1b   = (const float*)d_in[24];
        n2g   = (const float*)d_in[25];  n2b   = (const float*)d_in[26];
        n3g   = (const float*)d_in[27];  n3b   = (const float*)d_in[28];
        fc_w  = (const float*)d_in[29];  fc_b  = (const float*)d_in[30];
    }
    float* out = (float*)d_out;

    float *x, *enc, *q, *k, *v, *tmp;
    cudaGetSymbolAddress((void**)&x,    g_x);
    cudaGetSymbolAddress((void**)&enc,  g_enc);
    cudaGetSymbolAddress((void**)&q,    g_q);
    cudaGetSymbolAddress((void**)&k,    g_k);
    cudaGetSymbolAddress((void**)&v,    g_v);
    cudaGetSymbolAddress((void**)&tmp,  g_tmp);

    __nv_bfloat16 *whi, *wlo, *xhi, *xlo, *athi, *atlo, *ffhi, *fflo, *ehi, *elo;
    cudaGetSymbolAddress((void**)&whi,  g_whi);
    cudaGetSymbolAddress((void**)&wlo,  g_wlo);
    cudaGetSymbolAddress((void**)&xhi,  g_xhi);
    cudaGetSymbolAddress((void**)&xlo,  g_xlo);
    cudaGetSymbolAddress((void**)&athi, g_athi);
    cudaGetSymbolAddress((void**)&atlo, g_atlo);
    cudaGetSymbolAddress((void**)&ffhi, g_ffhi);
    cudaGetSymbolAddress((void**)&fflo, g_fflo);
    cudaGetSymbolAddress((void**)&ehi,  g_ehi);
    cudaGetSymbolAddress((void**)&elo,  g_elo);

    cudaFuncSetAttribute(gemm_mma<false,false>, cudaFuncAttributeMaxDynamicSharedMemorySize, GSMEM);
    cudaFuncSetAttribute(gemm_mma<true,true>,   cudaFuncAttributeMaxDynamicSharedMemorySize, GSMEM);

    // ---- weight prep: transpose + hi/lo split into [N][K] bf16 ----
    {
        const float* attn_w[8] = {sa_wq, sa_wk, sa_wv, sa_wo, ca_wq, ca_wk, ca_wv, ca_wo};
        dim3 thr(32, 8);
        for (int t = 0; t < 8; t++)
            for (int l = 0; l < NLAYER; l++) {
                size_t off = (size_t)t * ATTN_T_STRIDE + (size_t)l * ATTN_L_STRIDE;
                transpose_split<<<dim3(32, 32), thr>>>(
                    attn_w[t] + (size_t)l * D_MODEL * D_MODEL,
                    whi + off, wlo + off, D_MODEL, D_MODEL);
            }
        for (int l = 0; l < NLAYER; l++) {
            size_t off = W1_OFF + (size_t)l * 4194304ULL;
            transpose_split<<<dim3(FF_DIM/32, D_MODEL/32), thr>>>(
                w1 + (size_t)l * D_MODEL * FF_DIM, whi + off, wlo + off, D_MODEL, FF_DIM);
            off = W2_OFF + (size_t)l * 4194304ULL;
            transpose_split<<<dim3(D_MODEL/32, FF_DIM/32), thr>>>(
                w2 + (size_t)l * FF_DIM * D_MODEL, whi + off, wlo + off, FF_DIM, D_MODEL);
        }
        transpose_split<<<dim3(VOCAB/32, D_MODEL/32), thr>>>(
            fc_w, whi + FC_OFF, wlo + FC_OFF, D_MODEL, VOCAB);
    }

    embed_kernel<<<ROWS_X, 256>>>(tgt, emb, x, xhi, xlo);
    encpe_kernel<<<ROWS_E, 256>>>(src, enc);
    split_act<<<(ROWS_E*D_MODEL + 255)/256, 256>>>(enc, ehi, elo, ROWS_E*D_MODEL);

    for (int l = 0; l < NLAYER; l++) {
        const size_t bo  = (size_t)l * D_MODEL;
        const size_t b1o = (size_t)l * FF_DIM;
        const size_t wA  = (size_t)l * ATTN_L_STRIDE;
        #define WT(t) (whi + (size_t)(t) * ATTN_T_STRIDE + wA), (wlo + (size_t)(t) * ATTN_T_STRIDE + wA)

        // ---- self attention ----
        launch_gemm<false,false>(xhi, xlo, WT(0), sa_bq + bo, q, nullptr, nullptr, ROWS_X, D_MODEL, D_MODEL);
        launch_gemm<false,false>(xhi, xlo, WT(1), sa_bk + bo, k, nullptr, nullptr, ROWS_X, D_MODEL, D_MODEL);
        launch_gemm<false,false>(xhi, xlo, WT(2), sa_bv + bo, v, nullptr, nullptr, ROWS_X, D_MODEL, D_MODEL);
        attn_kernel<true><<<dim3(TGT / 8, NHEAD, BATCH), 256>>>(q, k, v, tgt, athi, atlo, TGT);
        launch_gemm<false,false>(athi, atlo, WT(3), sa_bo + bo, tmp, nullptr, nullptr, ROWS_X, D_MODEL, D_MODEL);
        add_ln_kernel<<<ROWS_X, 256>>>(x, tmp, n1g + bo, n1b + bo, xhi, xlo);

        // ---- cross attention ----
        launch_gemm<false,false>(xhi, xlo, WT(4), ca_bq + bo, q, nullptr, nullptr, ROWS_X, D_MODEL, D_MODEL);
        launch_gemm<false,false>(ehi, elo, WT(5), ca_bk + bo, k, nullptr, nullptr, ROWS_E, D_MODEL, D_MODEL);
        launch_gemm<false,false>(ehi, elo, WT(6), ca_bv + bo, v, nullptr, nullptr, ROWS_E, D_MODEL, D_MODEL);
        attn_kernel<false><<<dim3(TGT / 8, NHEAD, BATCH), 256>>>(q, k, v, nullptr, athi, atlo, SRCL);
        launch_gemm<false,false>(athi, atlo, WT(7), ca_bo + bo, tmp, nullptr, nullptr, ROWS_X, D_MODEL, D_MODEL);
        add_ln_kernel<<<ROWS_X, 256>>>(x, tmp, n2g + bo, n2b + bo, xhi, xlo);

        // ---- feed forward ----
        launch_gemm<true,true>(xhi, xlo, whi + W1_OFF + (size_t)l * 4194304ULL,
                               wlo + W1_OFF + (size_t)l * 4194304ULL,
                               b1 + b1o, nullptr, ffhi, fflo, ROWS_X, FF_DIM, D_MODEL);
        launch_gemm<false,false>(ffhi, fflo, whi + W2_OFF + (size_t)l * 4194304ULL,
                                 wlo + W2_OFF + (size_t)l * 4194304ULL,
                                 b2 + bo, tmp, nullptr, nullptr, ROWS_X, D_MODEL, FF_DIM);
        add_ln_kernel<<<ROWS_X, 256>>>(x, tmp, n3g + bo, n3b + bo, xhi, xlo);
        #undef WT
    }

    // ---- final projection to vocab ----
    launch_gemm<false,false>(xhi, xlo, whi + FC_OFF, wlo + FC_OFF, fc_b, out,
                             nullptr, nullptr, ROWS_X, VOCAB, D_MODEL);
}